// round 1
// baseline (speedup 1.0000x reference)
#include <cuda_runtime.h>
#include <cuda_bf16.h>

// ForwardKinematics: B=524288, NA=7 joints, NJ=8 transforms.
// out[n] = M0*M1*...*M6*F7, Mi = Fi * [[R(theta_i, a_i), 0],[0,1]]
// Rodrigues: R = I + s*K + (1-c)*K^2, K^2 = a a^T - I (unit axis)
// => rot(Mi) = A_i + s*(A_i K_i) + (1-c)*(A_i a a^T - A_i), trans(Mi) = t_i
// Per-joint constant matrices precomputed once per block into shared memory.

#define NB 524288
#define NACT 7
#define THREADS 256

__global__ __launch_bounds__(THREADS)
void fk_kernel(const float* __restrict__ jp,    // (B,7)
               const float* __restrict__ ft,    // (8,4,4)
               const float* __restrict__ axes,  // (7,3)
               float* __restrict__ out,         // (B,4,4)
               int n)
{
    // per-joint: A[9], B=A@K [9], C=A@(aa^T - I) [9], t[3]  -> 30 floats
    __shared__ float sj[NACT][30];
    __shared__ float sF7[12];

    const int tid = threadIdx.x;

    if (tid < NACT) {
        const float* F = ft + tid * 16;
        float A[9];
        #pragma unroll
        for (int r = 0; r < 3; r++)
            #pragma unroll
            for (int c = 0; c < 3; c++)
                A[r * 3 + c] = F[r * 4 + c];
        const float ax = axes[tid * 3 + 0];
        const float ay = axes[tid * 3 + 1];
        const float az = axes[tid * 3 + 2];
        float* d = sj[tid];
        #pragma unroll
        for (int k = 0; k < 9; k++) d[k] = A[k];
        // B = A @ K,  K = [[0,-z,y],[z,0,-x],[-y,x,0]]
        #pragma unroll
        for (int r = 0; r < 3; r++) {
            d[9 + r * 3 + 0] = A[r * 3 + 1] * az - A[r * 3 + 2] * ay;
            d[9 + r * 3 + 1] = A[r * 3 + 2] * ax - A[r * 3 + 0] * az;
            d[9 + r * 3 + 2] = A[r * 3 + 0] * ay - A[r * 3 + 1] * ax;
        }
        // C = A @ (a a^T - I)
        #pragma unroll
        for (int r = 0; r < 3; r++) {
            float dp = A[r * 3 + 0] * ax + A[r * 3 + 1] * ay + A[r * 3 + 2] * az;
            d[18 + r * 3 + 0] = dp * ax - A[r * 3 + 0];
            d[18 + r * 3 + 1] = dp * ay - A[r * 3 + 1];
            d[18 + r * 3 + 2] = dp * az - A[r * 3 + 2];
        }
        d[27] = F[3]; d[28] = F[7]; d[29] = F[11];
    }
    if (tid < 12) {
        sF7[tid] = ft[7 * 16 + tid];  // top 3 rows of F7, row-major 3x4
    }
    __syncthreads();

    const int n_idx = blockIdx.x * THREADS + tid;
    if (n_idx >= n) return;

    const float* p = jp + (size_t)n_idx * NACT;
    float th[NACT];
    #pragma unroll
    for (int i = 0; i < NACT; i++) th[i] = p[i];

    float Tr[9], Tt[3];

    // joint 0: T = M0
    {
        float s, c;
        __sincosf(th[0], &s, &c);
        const float o = 1.0f - c;
        const float* d = sj[0];
        #pragma unroll
        for (int k = 0; k < 9; k++)
            Tr[k] = d[k] + s * d[9 + k] + o * d[18 + k];
        Tt[0] = d[27]; Tt[1] = d[28]; Tt[2] = d[29];
    }

    // joints 1..6: T = T @ Mi
    #pragma unroll
    for (int i = 1; i < NACT; i++) {
        float s, c;
        __sincosf(th[i], &s, &c);
        const float o = 1.0f - c;
        const float* d = sj[i];
        float M[9];
        #pragma unroll
        for (int k = 0; k < 9; k++)
            M[k] = d[k] + s * d[9 + k] + o * d[18 + k];

        float R[9];
        #pragma unroll
        for (int r = 0; r < 3; r++)
            #pragma unroll
            for (int c2 = 0; c2 < 3; c2++)
                R[r * 3 + c2] = Tr[r * 3 + 0] * M[0 + c2]
                              + Tr[r * 3 + 1] * M[3 + c2]
                              + Tr[r * 3 + 2] * M[6 + c2];

        const float tx = d[27], ty = d[28], tz = d[29];
        #pragma unroll
        for (int r = 0; r < 3; r++)
            Tt[r] += Tr[r * 3 + 0] * tx + Tr[r * 3 + 1] * ty + Tr[r * 3 + 2] * tz;

        #pragma unroll
        for (int k = 0; k < 9; k++) Tr[k] = R[k];
    }

    // final: T = T @ F7 (general 3x4 top)
    float Rr[9], Ot[3];
    #pragma unroll
    for (int r = 0; r < 3; r++) {
        #pragma unroll
        for (int c2 = 0; c2 < 3; c2++)
            Rr[r * 3 + c2] = Tr[r * 3 + 0] * sF7[0 + c2]
                           + Tr[r * 3 + 1] * sF7[4 + c2]
                           + Tr[r * 3 + 2] * sF7[8 + c2];
        Ot[r] = Tt[r] + Tr[r * 3 + 0] * sF7[3]
                      + Tr[r * 3 + 1] * sF7[7]
                      + Tr[r * 3 + 2] * sF7[11];
    }

    float4* o = reinterpret_cast<float4*>(out + (size_t)n_idx * 16);
    o[0] = make_float4(Rr[0], Rr[1], Rr[2], Ot[0]);
    o[1] = make_float4(Rr[3], Rr[4], Rr[5], Ot[1]);
    o[2] = make_float4(Rr[6], Rr[7], Rr[8], Ot[2]);
    o[3] = make_float4(0.0f, 0.0f, 0.0f, 1.0f);
}

extern "C" void kernel_launch(void* const* d_in, const int* in_sizes, int n_in,
                              void* d_out, int out_size) {
    const float* jp   = (const float*)d_in[0];  // joint_positions (B,7)
    const float* ft   = (const float*)d_in[1];  // fixed_transforms (8,4,4)
    const float* axes = (const float*)d_in[2];  // joint_axes (7,3)
    float* out = (float*)d_out;
    const int n = in_sizes[0] / NACT;
    const int blocks = (n + THREADS - 1) / THREADS;
    fk_kernel<<<blocks, THREADS>>>(jp, ft, axes, out, n);
}